// round 14
// baseline (speedup 1.0000x reference)
#include <cuda_runtime.h>
#include <cuda_bf16.h>
#include <cstdint>
#include <cstddef>

#define FULLMASK 0xffffffffu
typedef unsigned long long u64;

namespace cfg {
constexpr int B = 4, N = 16384, S = 2048, K = 32;
constexpr int NN = B * S * K;           // 262144 columns
constexpr int BS = B * S;               // 8192 groups
constexpr float R2 = 0.2f * 0.2f;
constexpr float EPS = 1e-5f;
constexpr int FPS_CTAS = 8;             // CTAs per cluster (per batch)
constexpr int FPS_PTS  = 2048;          // points per CTA
constexpr int FPS_THR  = 256;           // 8 warps, 2/SMSP
}

// ---------------- static scratch (no allocations allowed) ----------------
__device__ int   g_idxc[cfg::BS];
__device__ float g_newxyz[cfg::BS * 3];
__device__ int   g_ballidx[(size_t)cfg::BS * cfg::K];
__device__ float g_x1[(size_t)64  * cfg::NN];   //  64 MB
__device__ float g_x2[(size_t)128 * cfg::NN];   // 128 MB
__device__ float g_max[(size_t)256 * cfg::BS];  // 8 MB: per (ch, group) raw max
__device__ float g_psum[2048 * 256];            // chunk-major (coalesced fin)
__device__ float g_psq [2048 * 256];
__device__ float g_A [256];
__device__ float g_Bc[256];

// f32x2 helpers (per-lane IEEE identical to scalar ops)
#define PACK2(dst, f) asm("mov.b64 %0, {%1, %1};" : "=l"(dst) : "r"(__float_as_uint(f)))
#define PACK2V(dst, lo, hi) asm("mov.b64 %0, {%1, %2};" : "=l"(dst) : "r"(__float_as_uint(lo)), "r"(__float_as_uint(hi)))
#define UNPACK2(lo, hi, v) asm("mov.b64 {%0, %1}, %2;" : "=r"(lo), "=r"(hi) : "l"(v))
#define ADD2(d, a, b) asm("add.rn.f32x2 %0, %1, %2;" : "=l"(d) : "l"(a), "l"(b))
#define MUL2(d, a, b) asm("mul.rn.f32x2 %0, %1, %2;" : "=l"(d) : "l"(a), "l"(b))
#define FFMA2(d, a, b, c) asm("fma.rn.f32x2 %0, %1, %2, %3;" : "=l"(d) : "l"(a), "l"(b), "l"(c))
static __device__ __forceinline__ float lo32(u64 v) { return __uint_as_float((unsigned)v); }
static __device__ __forceinline__ float hi32(u64 v) { return __uint_as_float((unsigned)(v >> 32)); }

// exact first-max warp argmax via 2x redux (dist bits, then ~idx of ties)
static __device__ __forceinline__ u64 warp_max_key(u64 key)
{
    unsigned hi = (unsigned)(key >> 32), lo = (unsigned)key;
    unsigned wh = __reduce_max_sync(FULLMASK, hi);
    unsigned cand = (hi == wh) ? lo : 0u;
    unsigned wl = __reduce_max_sync(FULLMASK, cand);
    return ((u64)wh << 32) | wl;
}

// packed distance + d=min(d,t) + serial first-max argmax (ascending idx)
static __device__ __forceinline__ u64 update_argmax(
    const u64 (&ppx)[4], const u64 (&ppy)[4], const u64 (&ppz)[4],
    float (&d)[8], float cx, float cy, float cz, int base, int tid)
{
    u64 ncx, ncy, ncz;
    PACK2(ncx, -cx); PACK2(ncy, -cy); PACK2(ncz, -cz);
    float t[8];
#pragma unroll
    for (int p = 0; p < 4; ++p) {
        u64 dx, dy, dz, xx, yy, zz, ss, tt;
        ADD2(dx, ppx[p], ncx);
        ADD2(dy, ppy[p], ncy);
        ADD2(dz, ppz[p], ncz);
        MUL2(xx, dx, dx);
        MUL2(yy, dy, dy);
        MUL2(zz, dz, dz);
        ADD2(ss, xx, yy);
        ADD2(tt, ss, zz);
        unsigned t0b, t1b;
        UNPACK2(t0b, t1b, tt);
        t[2 * p]     = __uint_as_float(t0b);
        t[2 * p + 1] = __uint_as_float(t1b);
    }
    float bv = -1.0f; unsigned bi = 0u;
#pragma unroll
    for (int j = 0; j < 8; ++j) {
        d[j] = fminf(d[j], t[j]);
        if (d[j] > bv) { bv = d[j]; bi = (unsigned)(base + j * cfg::FPS_THR + tid); }
    }
    return ((u64)__float_as_uint(bv) << 32) | (u64)(0xffffffffu - bi);
}

// profiling-window shim (keeps fps_kernel in the fixed ncu capture slot)
__global__ void noop_kernel(int) {}

// =====================================================================
// 1) FPS (R13-proven): 8-CTA cluster, 256 thr, 8 pts/thread, redux
//    reductions, single-waiter mbarrier exchange.
// =====================================================================
__global__ void __cluster_dims__(cfg::FPS_CTAS, 1, 1) __launch_bounds__(cfg::FPS_THR, 1)
fps_kernel(const float* __restrict__ pos)
{
    using namespace cfg;
    const int batch = blockIdx.x / FPS_CTAS;
    const int rank  = blockIdx.x % FPS_CTAS;
    const int tid   = threadIdx.x;
    const int lane  = tid & 31;
    const int wid   = tid >> 5;                 // 0..7
    const int base  = rank * FPS_PTS;

    const float* pb = pos + (size_t)batch * N * 3;

    extern __shared__ char dsm[];
    float* s_px = (float*)dsm;                       // [2048]
    float* s_py = s_px + FPS_PTS;
    float* s_pz = s_py + FPS_PTS;
    u64*   s_warp = (u64*)(s_pz + FPS_PTS);          // [8]
    u64*   s_key  = s_warp + 8;                      // [2][8]
    float* s_cx   = (float*)(s_key + 16);            // [2][8]
    float* s_cy   = s_cx + 16;
    float* s_cz   = s_cy + 16;
    u64*   s_mbar = (u64*)(s_cz + 16);               // [2]

    // load 8 points/thread; pack pairs (lo=2p, hi=2p+1, ascending idx)
    u64 ppx[4], ppy[4], ppz[4];
    float d[8];
#pragma unroll
    for (int p = 0; p < 4; ++p) {
        int i0 = base + (2 * p) * FPS_THR + tid;
        int i1 = base + (2 * p + 1) * FPS_THR + tid;
        float x0 = pb[i0 * 3 + 0], y0 = pb[i0 * 3 + 1], z0 = pb[i0 * 3 + 2];
        float x1 = pb[i1 * 3 + 0], y1 = pb[i1 * 3 + 1], z1 = pb[i1 * 3 + 2];
        s_px[(2 * p) * FPS_THR + tid] = x0;
        s_py[(2 * p) * FPS_THR + tid] = y0;
        s_pz[(2 * p) * FPS_THR + tid] = z0;
        s_px[(2 * p + 1) * FPS_THR + tid] = x1;
        s_py[(2 * p + 1) * FPS_THR + tid] = y1;
        s_pz[(2 * p + 1) * FPS_THR + tid] = z1;
        PACK2V(ppx[p], x0, x1);
        PACK2V(ppy[p], y0, y1);
        PACK2V(ppz[p], z0, z1);
        d[2 * p] = 1e10f; d[2 * p + 1] = 1e10f;
    }

    const uint32_t mb0 = (uint32_t)__cvta_generic_to_shared(&s_mbar[0]);
    const uint32_t mb1 = (uint32_t)__cvta_generic_to_shared(&s_mbar[1]);
    if (tid == 0) {
        asm volatile("mbarrier.init.shared.b64 [%0], %1;" :: "r"(mb0), "r"((unsigned)FPS_CTAS) : "memory");
        asm volatile("mbarrier.init.shared.b64 [%0], %1;" :: "r"(mb1), "r"((unsigned)FPS_CTAS) : "memory");
    }
    __syncthreads();
    asm volatile("barrier.cluster.arrive.aligned;" ::: "memory");
    asm volatile("barrier.cluster.wait.aligned;"   ::: "memory");

    // warp0 lanes 0..7 publish to CTA 'lane'; remote addrs loop-invariant
    uint32_t rk[2], rx[2], ry[2], rz[2], rm[2];
    if (wid == 0 && lane < FPS_CTAS) {
#pragma unroll
        for (int par = 0; par < 2; ++par) {
            uint32_t a;
            a = (uint32_t)__cvta_generic_to_shared(&s_key[par * FPS_CTAS + rank]);
            asm("mapa.shared::cluster.u32 %0, %1, %2;" : "=r"(rk[par]) : "r"(a), "r"(lane));
            a = (uint32_t)__cvta_generic_to_shared(&s_cx[par * FPS_CTAS + rank]);
            asm("mapa.shared::cluster.u32 %0, %1, %2;" : "=r"(rx[par]) : "r"(a), "r"(lane));
            a = (uint32_t)__cvta_generic_to_shared(&s_cy[par * FPS_CTAS + rank]);
            asm("mapa.shared::cluster.u32 %0, %1, %2;" : "=r"(ry[par]) : "r"(a), "r"(lane));
            a = (uint32_t)__cvta_generic_to_shared(&s_cz[par * FPS_CTAS + rank]);
            asm("mapa.shared::cluster.u32 %0, %1, %2;" : "=r"(rz[par]) : "r"(a), "r"(lane));
            a = (par == 0) ? mb0 : mb1;
            asm("mapa.shared::cluster.u32 %0, %1, %2;" : "=r"(rm[par]) : "r"(a), "r"(lane));
        }
    }

    // prologue: centroid 0 = point 0
    if (rank == 0 && tid == 0) g_idxc[batch * S] = 0;
    {
        u64 key = update_argmax(ppx, ppy, ppz, d, pb[0], pb[1], pb[2], base, tid);
        key = warp_max_key(key);
        if (lane == 0) s_warp[wid] = key;
    }

    for (int s = 0; s < S - 1; ++s) {
        __syncthreads();   // (A) — s_warp complete (8 warps)

        const int par = s & 1;
        if (wid == 0) {
            // block winner: 8 warp keys -> redux pair (exact tie-break)
            u64 kl = warp_max_key(s_warp[lane & 7]);
            if (lane < FPS_CTAS) {
                unsigned widx = 0xffffffffu - (unsigned)kl;
                int loc = (int)widx - base;
                float wx = s_px[loc], wy = s_py[loc], wz = s_pz[loc];
                asm volatile("st.shared::cluster.b64 [%0], %1;" :: "r"(rk[par]), "l"(kl) : "memory");
                asm volatile("st.shared::cluster.b32 [%0], %1;" :: "r"(rx[par]), "r"(__float_as_uint(wx)) : "memory");
                asm volatile("st.shared::cluster.b32 [%0], %1;" :: "r"(ry[par]), "r"(__float_as_uint(wy)) : "memory");
                asm volatile("st.shared::cluster.b32 [%0], %1;" :: "r"(rz[par]), "r"(__float_as_uint(wz)) : "memory");
                asm volatile("mbarrier.arrive.release.cluster.shared::cluster.b64 _, [%0];"
                             :: "r"(rm[par]) : "memory");
            }
            // single-waiter cluster-scope acquire (warp0 only)
            {
                const uint32_t mb = par ? mb1 : mb0;
                const uint32_t ph = (unsigned)(s >> 1) & 1u;
                uint32_t done;
                asm volatile(
                    "{\n\t.reg .pred p;\n\t"
                    "mbarrier.try_wait.parity.acquire.cluster.shared::cta.b64 p, [%1], %2;\n\t"
                    "selp.b32 %0, 1, 0, p;\n\t}"
                    : "=r"(done) : "r"(mb), "r"(ph) : "memory");
                if (!done) {
                    asm volatile(
                        "{\n\t.reg .pred P1;\n\t"
                        "WL%=:\n\t"
                        "mbarrier.try_wait.parity.acquire.cluster.shared::cta.b64 P1, [%0], %1, 0x989680;\n\t"
                        "@P1 bra.uni WD%=;\n\t"
                        "bra.uni WL%=;\n\t"
                        "WD%=:\n\t}"
                        :: "r"(mb), "r"(ph) : "memory");
                }
            }
        }
        __syncthreads();   // (B) — CTA fence releases remote slots to all warps

        // winner among 8 CTA candidates
        u64 bk = s_key[par * FPS_CTAS];
        int br = 0;
#pragma unroll
        for (int r = 1; r < FPS_CTAS; ++r) {
            u64 kk = s_key[par * FPS_CTAS + r];
            if (kk > bk) { bk = kk; br = r; }
        }
        if (rank == 0 && tid == 0)
            g_idxc[batch * S + s + 1] = (int)(0xffffffffu - (unsigned)bk);
        float cx = s_cx[par * FPS_CTAS + br];
        float cy = s_cy[par * FPS_CTAS + br];
        float cz = s_cz[par * FPS_CTAS + br];

        u64 key = update_argmax(ppx, ppy, ppz, d, cx, cy, cz, base, tid);
        key = warp_max_key(key);
        if (lane == 0) s_warp[wid] = key;
    }
}

// =====================================================================
// 2) gather centroids: new_xyz + transposed block of the output
// =====================================================================
__global__ void __launch_bounds__(256)
gather_kernel(const float* __restrict__ pos, float* __restrict__ out)
{
    using namespace cfg;
    int t = blockIdx.x * 256 + threadIdx.x;       // b*S+s
    int b = t / S, s = t - b * S;
    int id = g_idxc[t];
    const float* p = pos + ((size_t)b * N + id) * 3;
    float x = p[0], y = p[1], z = p[2];
    g_newxyz[t * 3 + 0] = x;
    g_newxyz[t * 3 + 1] = y;
    g_newxyz[t * 3 + 2] = z;
    out[((size_t)b * 3 + 0) * S + s] = x;
    out[((size_t)b * 3 + 1) * S + s] = y;
    out[((size_t)b * 3 + 2) * S + s] = z;
}

// =====================================================================
// 3) ball query: warp per centroid; first K in-radius indices ascending
// =====================================================================
__global__ void __launch_bounds__(256)
ballq_kernel(const float* __restrict__ pos)
{
    using namespace cfg;
    int g = blockIdx.x * 8 + (threadIdx.x >> 5);  // b*S+s
    int lane = threadIdx.x & 31;
    int b = g / S;
    float cx = g_newxyz[g * 3 + 0];
    float cy = g_newxyz[g * 3 + 1];
    float cz = g_newxyz[g * 3 + 2];
    float cn = __fadd_rn(__fadd_rn(__fmul_rn(cx, cx), __fmul_rn(cy, cy)), __fmul_rn(cz, cz));
    const float* pb = pos + (size_t)b * N * 3;
    int* outp = g_ballidx + (size_t)g * K;

    int filled = 0;
    int first = -1;
    for (int p0 = 0; p0 < N && filled < K; p0 += 32) {
        int p = p0 + lane;
        float px = pb[p * 3 + 0], py = pb[p * 3 + 1], pz = pb[p * 3 + 2];
        float pn = __fadd_rn(__fadd_rn(__fmul_rn(px, px), __fmul_rn(py, py)), __fmul_rn(pz, pz));
        float dot = __fadd_rn(__fadd_rn(__fmul_rn(cx, px), __fmul_rn(cy, py)), __fmul_rn(cz, pz));
        float sq = __fadd_rn(__fadd_rn(cn, pn), -__fmul_rn(2.0f, dot));
        bool incl = !(sq > R2);
        unsigned mask = __ballot_sync(FULLMASK, incl);
        if (first < 0 && mask) first = p0 + (__ffs(mask) - 1);
        int rnk = filled + __popc(mask & ((1u << lane) - 1u));
        if (incl && rnk < K) outp[rnk] = p;
        filled += __popc(mask);
    }
    if (first < 0) first = 0;
    if (filled < K)
        for (int j = filled + lane; j < K; j += 32) outp[j] = first;
}

// =====================================================================
// 4) layer1: gather groups + conv 6->64 (raw conv output, bias included)
// =====================================================================
__global__ void __launch_bounds__(256)
layer1_kernel(const float* __restrict__ pos, const float* __restrict__ feats,
              const float* __restrict__ w1, const float* __restrict__ b1)
{
    using namespace cfg;
    __shared__ float ws[64 * 6];
    __shared__ float bs[64];
    for (int i = threadIdx.x; i < 64 * 6; i += 256) ws[i] = w1[i];
    if (threadIdx.x < 64) bs[threadIdx.x] = b1[threadIdx.x];
    __syncthreads();

    int g = blockIdx.x * 8 + (threadIdx.x >> 5);  // b*S+s
    int lane = threadIdx.x & 31;                  // k within group
    int b = g / S;
    int id = g_ballidx[(size_t)g * K + lane];
    const float* p = pos   + ((size_t)b * N + id) * 3;
    const float* f = feats + ((size_t)b * N + id) * 3;
    float c0 = p[0] - g_newxyz[g * 3 + 0];
    float c1 = p[1] - g_newxyz[g * 3 + 1];
    float c2 = p[2] - g_newxyz[g * 3 + 2];
    float c3 = f[0], c4 = f[1], c5 = f[2];
    size_t ncol = (size_t)g * K + lane;
#pragma unroll
    for (int o = 0; o < 64; ++o) {
        const float* w = ws + o * 6;
        float acc = bs[o];
        acc = fmaf(w[0], c0, acc);
        acc = fmaf(w[1], c1, acc);
        acc = fmaf(w[2], c2, acc);
        acc = fmaf(w[3], c3, acc);
        acc = fmaf(w[4], c4, acc);
        acc = fmaf(w[5], c5, acc);
        g_x1[(size_t)o * NN + ncol] = acc;
    }
}

// =====================================================================
// 5) layer1 per-channel partial sums (64 chunks of 4096), chunk-major out
// =====================================================================
__global__ void __launch_bounds__(256)
stats_part1_kernel()
{
    using namespace cfg;
    int c = blockIdx.y, chunk = blockIdx.x;
    const float* p = g_x1 + (size_t)c * NN + (size_t)chunk * 4096;
    int t = threadIdx.x;
    float s = 0.f, q = 0.f;
#pragma unroll
    for (int i = 0; i < 4; ++i) {
        float4 v = *(const float4*)&p[i * 1024 + t * 4];
        s += v.x; s += v.y; s += v.z; s += v.w;
        q += v.x * v.x; q += v.y * v.y; q += v.z * v.z; q += v.w * v.w;
    }
#pragma unroll
    for (int off = 16; off; off >>= 1) {
        s += __shfl_down_sync(FULLMASK, s, off);
        q += __shfl_down_sync(FULLMASK, q, off);
    }
    __shared__ float ss[8], qq[8];
    if ((t & 31) == 0) { ss[t >> 5] = s; qq[t >> 5] = q; }
    __syncthreads();
    if (t == 0) {
        float S2 = 0.f, Q2 = 0.f;
#pragma unroll
        for (int i = 0; i < 8; ++i) { S2 += ss[i]; Q2 += qq[i]; }
        g_psum[chunk * 256 + c] = S2;   // chunk-major: coalesced finalize
        g_psq [chunk * 256 + c] = Q2;
    }
}

// finalize: mu, var -> folded scale/shift  y = relu(A*x + Bc)
template<int NPART>
__global__ void __launch_bounds__(256)
stats_fin_kernel(const float* __restrict__ gamma, const float* __restrict__ beta, int C)
{
    using namespace cfg;
    int c = blockIdx.x * 256 + threadIdx.x;
    if (c >= C) return;
    float s = 0.f, q = 0.f;
#pragma unroll 8
    for (int i = 0; i < NPART; ++i) { s += g_psum[i * 256 + c]; q += g_psq[i * 256 + c]; }
    const float inv = 1.0f / (float)NN;   // 2^-18, exact
    float mu  = s * inv;
    float var = q * inv - mu * mu;
    float rs  = rsqrtf(var + EPS);
    float A   = gamma[c] * rs;
    g_A[c]  = A;
    g_Bc[c] = beta[c] - mu * A;
}

// =====================================================================
// 6) GEMM: double-buffered smem pipeline (1 sync/kt, LDG overlapped),
//    128x128 tile, FFMA2 inner loop. Arithmetic identical to R9/R13.
// =====================================================================
template<int LAYER>
__global__ void __launch_bounds__(256)
gemm_kernel(const float* __restrict__ W, const float* __restrict__ bias)
{
    using namespace cfg;
    constexpr int Cin = (LAYER == 2) ? 64 : 128;
    constexpr int NKT = Cin / 8;
    const float* __restrict__ X = (LAYER == 2) ? g_x1 : g_x2;
    float* __restrict__ Y       = g_x2;   // only used for LAYER==2

    __shared__ float sA[2][8][128];
    __shared__ float sB[2][8][132];
    const int tid = threadIdx.x;
    const int n0 = blockIdx.x * 128;
    const int m0 = blockIdx.y * 128;
    const int tm = (tid >> 4) << 3;
    const int tn = (tid & 15) << 3;

    u64 acc2[8][4];
#pragma unroll
    for (int i = 0; i < 8; ++i) {
        float bv = bias[m0 + tm + i];
        u64 p; PACK2(p, bv);
#pragma unroll
        for (int j = 0; j < 4; ++j) acc2[i][j] = p;
    }

    const int kload_m = tid >> 1;            // 0..127
    const int kload_k = (tid & 1) << 2;      // 0 or 4
    const int bload_k = tid >> 5;            // 0..7
    const int bload_n = (tid & 31) << 2;     // 0..124

    // ---- prologue: load kt=0 and stage into buffer 0 ----
    {
        float4 wv = *(const float4*)&W[(size_t)(m0 + kload_m) * Cin + kload_k];
        float a_s = g_A [bload_k];
        float b_s = g_Bc[bload_k];
        float4 xv = *(const float4*)&X[(size_t)bload_k * NN + n0 + bload_n];
        sA[0][kload_k + 0][kload_m] = wv.x;
        sA[0][kload_k + 1][kload_m] = wv.y;
        sA[0][kload_k + 2][kload_m] = wv.z;
        sA[0][kload_k + 3][kload_m] = wv.w;
        float4 yv;
        yv.x = fmaxf(fmaf(a_s, xv.x, b_s), 0.f);
        yv.y = fmaxf(fmaf(a_s, xv.y, b_s), 0.f);
        yv.z = fmaxf(fmaf(a_s, xv.z, b_s), 0.f);
        yv.w = fmaxf(fmaf(a_s, xv.w, b_s), 0.f);
        *(float4*)&sB[0][bload_k][bload_n] = yv;
    }
    __syncthreads();

    for (int it = 0; it < NKT; ++it) {
        const int cur = it & 1;
        // prefetch kt = it+1 into registers (LDG latency hidden by compute)
        float4 wv, xv; float a_s = 0.f, b_s = 0.f;
        if (it + 1 < NKT) {
            const int kt = (it + 1) * 8;
            wv = *(const float4*)&W[(size_t)(m0 + kload_m) * Cin + kt + kload_k];
            a_s = g_A [kt + bload_k];
            b_s = g_Bc[kt + bload_k];
            xv = *(const float4*)&X[(size_t)(kt + bload_k) * NN + n0 + bload_n];
        }
        // compute on buffer `cur`
#pragma unroll
        for (int kk = 0; kk < 8; ++kk) {
            float av[8];
            *(float4*)(av)     = *(const float4*)&sA[cur][kk][tm];
            *(float4*)(av + 4) = *(const float4*)&sA[cur][kk][tm + 4];
            const u64* bp = (const u64*)&sB[cur][kk][tn];   // 32B-aligned
            u64 b2[4] = { bp[0], bp[1], bp[2], bp[3] };
#pragma unroll
            for (int i = 0; i < 8; ++i) {
                u64 a2; PACK2(a2, av[i]);
#pragma unroll
                for (int j = 0; j < 4; ++j)
                    FFMA2(acc2[i][j], a2, b2[j], acc2[i][j]);
            }
        }
        // stage prefetched tile into the other buffer
        if (it + 1 < NKT) {
            const int nxt = cur ^ 1;
            sA[nxt][kload_k + 0][kload_m] = wv.x;
            sA[nxt][kload_k + 1][kload_m] = wv.y;
            sA[nxt][kload_k + 2][kload_m] = wv.z;
            sA[nxt][kload_k + 3][kload_m] = wv.w;
            float4 yv;
            yv.x = fmaxf(fmaf(a_s, xv.x, b_s), 0.f);
            yv.y = fmaxf(fmaf(a_s, xv.y, b_s), 0.f);
            yv.z = fmaxf(fmaf(a_s, xv.z, b_s), 0.f);
            yv.w = fmaxf(fmaf(a_s, xv.w, b_s), 0.f);
            *(float4*)&sB[nxt][bload_k][bload_n] = yv;
        }
        __syncthreads();
    }

    // ----- epilogue: store (L2), stats partials (all), group max (L3) -----
    const int bx = blockIdx.x;
#pragma unroll
    for (int i = 0; i < 8; ++i) {
        float v[8];
        v[0] = lo32(acc2[i][0]); v[1] = hi32(acc2[i][0]);
        v[2] = lo32(acc2[i][1]); v[3] = hi32(acc2[i][1]);
        v[4] = lo32(acc2[i][2]); v[5] = hi32(acc2[i][2]);
        v[6] = lo32(acc2[i][3]); v[7] = hi32(acc2[i][3]);
        if constexpr (LAYER == 2) {
            size_t row = (size_t)(m0 + tm + i) * NN + n0 + tn;
            *(float4*)&Y[row]     = make_float4(v[0], v[1], v[2], v[3]);
            *(float4*)&Y[row + 4] = make_float4(v[4], v[5], v[6], v[7]);
        }
        float s = 0.f, q = 0.f;
#pragma unroll
        for (int j = 0; j < 8; ++j) { s += v[j]; q += v[j] * v[j]; }
#pragma unroll
        for (int off = 1; off < 16; off <<= 1) {
            s += __shfl_xor_sync(FULLMASK, s, off);
            q += __shfl_xor_sync(FULLMASK, q, off);
        }
        if ((tid & 15) == 0) {
            g_psum[bx * 256 + (m0 + tm + i)] = s;   // chunk-major
            g_psq [bx * 256 + (m0 + tm + i)] = q;
        }
        if constexpr (LAYER == 3) {
            float mx = v[0];
#pragma unroll
            for (int j = 1; j < 8; ++j) mx = fmaxf(mx, v[j]);
            mx = fmaxf(mx, __shfl_xor_sync(FULLMASK, mx, 1));
            mx = fmaxf(mx, __shfl_xor_sync(FULLMASK, mx, 2));
            if ((tid & 3) == 0)
                g_max[(size_t)(m0 + tm + i) * BS + (n0 >> 5) + ((tid & 15) >> 2)] = mx;
        }
    }
}

// =====================================================================
// 7) final: y = relu(A3*mx + B3) over the 8MB group-max buffer
// =====================================================================
__global__ void __launch_bounds__(256)
finalmax_kernel(float* __restrict__ out)
{
    using namespace cfg;
    int idx = blockIdx.x * 256 + threadIdx.x;   // c*8192 + bs
    int c  = idx >> 13;
    int bs = idx & 8191;
    float mx = g_max[(size_t)c * BS + bs];
    float y = fmaxf(fmaf(g_A[c], mx, g_Bc[c]), 0.f);
    int b = bs >> 11, s = bs & 2047;
    out[(size_t)B * 3 * S + ((size_t)b * 256 + c) * S + s] = y;
}

// =====================================================================
// launcher
// =====================================================================
extern "C" void kernel_launch(void* const* d_in, const int* in_sizes, int n_in,
                              void* d_out, int out_size)
{
    using namespace cfg;
    const float* pos   = (const float*)d_in[0];
    const float* feats = (const float*)d_in[1];
    const float* w1 = (const float*)d_in[2];
    const float* b1 = (const float*)d_in[3];
    const float* g1 = (const float*)d_in[4];
    const float* be1 = (const float*)d_in[5];
    const float* w2 = (const float*)d_in[6];
    const float* b2 = (const float*)d_in[7];
    const float* g2 = (const float*)d_in[8];
    const float* be2 = (const float*)d_in[9];
    const float* w3 = (const float*)d_in[10];
    const float* b3 = (const float*)d_in[11];
    const float* g3 = (const float*)d_in[12];
    const float* be3 = (const float*)d_in[13];
    float* out = (float*)d_out;

    const int fps_smem = 3 * FPS_PTS * 4 + 1024;
    cudaFuncSetAttribute(fps_kernel, cudaFuncAttributeMaxDynamicSharedMemorySize, fps_smem);

    // shims: keep fps_kernel in the fixed ncu capture slot
    noop_kernel<<<1, 32>>>(0);
    noop_kernel<<<1, 32>>>(0);
    noop_kernel<<<1, 32>>>(0);

    fps_kernel<<<B * FPS_CTAS, FPS_THR, fps_smem>>>(pos);
    gather_kernel<<<BS / 256, 256>>>(pos, out);
    ballq_kernel<<<BS / 8, 256>>>(pos);
    layer1_kernel<<<BS / 8, 256>>>(pos, feats, w1, b1);

    stats_part1_kernel<<<dim3(64, 64), 256>>>();
    stats_fin_kernel<64><<<1, 256>>>(g1, be1, 64);

    gemm_kernel<2><<<dim3(NN / 128, 1), 256>>>(w2, b2);
    stats_fin_kernel<2048><<<1, 256>>>(g2, be2, 128);

    gemm_kernel<3><<<dim3(NN / 128, 2), 256>>>(w3, b3);
    stats_fin_kernel<2048><<<1, 256>>>(g3, be3, 256);

    finalmax_kernel<<<(256 * BS) / 256, 256>>>(out);
}

// round 15
// speedup vs baseline: 1.1382x; 1.1382x over previous
#include <cuda_runtime.h>
#include <cuda_bf16.h>
#include <cstdint>
#include <cstddef>

#define FULLMASK 0xffffffffu
typedef unsigned long long u64;

namespace cfg {
constexpr int B = 4, N = 16384, S = 2048, K = 32;
constexpr int NN = B * S * K;           // 262144 columns
constexpr int BS = B * S;               // 8192 groups
constexpr float R2 = 0.2f * 0.2f;
constexpr float EPS = 1e-5f;
constexpr int FPS_CTAS = 8;             // CTAs per cluster (per batch)
constexpr int FPS_PTS  = 2048;          // points per CTA
constexpr int FPS_THR  = 256;           // 8 warps, 2/SMSP
}

// ---------------- static scratch (no allocations allowed) ----------------
__device__ int   g_idxc[cfg::BS];
__device__ float g_newxyz[cfg::BS * 3];
__device__ int   g_ballidx[(size_t)cfg::BS * cfg::K];
__device__ float g_x1[(size_t)64  * cfg::NN];   //  64 MB
__device__ float g_x2[(size_t)128 * cfg::NN];   // 128 MB
__device__ float g_max[(size_t)256 * cfg::BS];  // 8 MB: per (ch, group) raw max
__device__ float g_psum[2048 * 256];            // chunk-major (coalesced fin)
__device__ float g_psq [2048 * 256];
__device__ float g_A [256];
__device__ float g_Bc[256];

// f32x2 helpers (per-lane IEEE identical to scalar ops)
#define PACK2(dst, f) asm("mov.b64 %0, {%1, %1};" : "=l"(dst) : "r"(__float_as_uint(f)))
#define PACK2V(dst, lo, hi) asm("mov.b64 %0, {%1, %2};" : "=l"(dst) : "r"(__float_as_uint(lo)), "r"(__float_as_uint(hi)))
#define UNPACK2(lo, hi, v) asm("mov.b64 {%0, %1}, %2;" : "=r"(lo), "=r"(hi) : "l"(v))
#define ADD2(d, a, b) asm("add.rn.f32x2 %0, %1, %2;" : "=l"(d) : "l"(a), "l"(b))
#define MUL2(d, a, b) asm("mul.rn.f32x2 %0, %1, %2;" : "=l"(d) : "l"(a), "l"(b))
#define FFMA2(d, a, b, c) asm("fma.rn.f32x2 %0, %1, %2, %3;" : "=l"(d) : "l"(a), "l"(b), "l"(c))
static __device__ __forceinline__ float lo32(u64 v) { return __uint_as_float((unsigned)v); }
static __device__ __forceinline__ float hi32(u64 v) { return __uint_as_float((unsigned)(v >> 32)); }

// exact first-max warp argmax via 2x redux (dist bits, then ~idx of ties)
static __device__ __forceinline__ u64 warp_max_key(u64 key)
{
    unsigned hi = (unsigned)(key >> 32), lo = (unsigned)key;
    unsigned wh = __reduce_max_sync(FULLMASK, hi);
    unsigned cand = (hi == wh) ? lo : 0u;
    unsigned wl = __reduce_max_sync(FULLMASK, cand);
    return ((u64)wh << 32) | wl;
}

// packed distance + d=min(d,t) + serial first-max argmax (ascending idx)
static __device__ __forceinline__ u64 update_argmax(
    const u64 (&ppx)[4], const u64 (&ppy)[4], const u64 (&ppz)[4],
    float (&d)[8], float cx, float cy, float cz, int base, int tid)
{
    u64 ncx, ncy, ncz;
    PACK2(ncx, -cx); PACK2(ncy, -cy); PACK2(ncz, -cz);
    float t[8];
#pragma unroll
    for (int p = 0; p < 4; ++p) {
        u64 dx, dy, dz, xx, yy, zz, ss, tt;
        ADD2(dx, ppx[p], ncx);
        ADD2(dy, ppy[p], ncy);
        ADD2(dz, ppz[p], ncz);
        MUL2(xx, dx, dx);
        MUL2(yy, dy, dy);
        MUL2(zz, dz, dz);
        ADD2(ss, xx, yy);
        ADD2(tt, ss, zz);
        unsigned t0b, t1b;
        UNPACK2(t0b, t1b, tt);
        t[2 * p]     = __uint_as_float(t0b);
        t[2 * p + 1] = __uint_as_float(t1b);
    }
    float bv = -1.0f; unsigned bi = 0u;
#pragma unroll
    for (int j = 0; j < 8; ++j) {
        d[j] = fminf(d[j], t[j]);
        if (d[j] > bv) { bv = d[j]; bi = (unsigned)(base + j * cfg::FPS_THR + tid); }
    }
    return ((u64)__float_as_uint(bv) << 32) | (u64)(0xffffffffu - bi);
}

// profiling-window shim (keeps fps_kernel in the fixed ncu capture slot)
__global__ void noop_kernel(int) {}

// =====================================================================
// 1) FPS: 8-CTA cluster, 256 thr, 8 pts/thread, redux reductions,
//    single-waiter mbarrier exchange. KEY-ONLY publish (8B remote store);
//    coords resolved from a full local 16384-pt smem table (192KB).
// =====================================================================
__global__ void __cluster_dims__(cfg::FPS_CTAS, 1, 1) __launch_bounds__(cfg::FPS_THR, 1)
fps_kernel(const float* __restrict__ pos)
{
    using namespace cfg;
    const int batch = blockIdx.x / FPS_CTAS;
    const int rank  = blockIdx.x % FPS_CTAS;
    const int tid   = threadIdx.x;
    const int lane  = tid & 31;
    const int wid   = tid >> 5;                 // 0..7
    const int base  = rank * FPS_PTS;

    const float* pb = pos + (size_t)batch * N * 3;

    extern __shared__ char dsm[];
    float* s_fx = (float*)dsm;                       // [16384] full table
    float* s_fy = s_fx + N;
    float* s_fz = s_fy + N;
    u64*   s_warp = (u64*)(s_fz + N);                // [8]
    u64*   s_key  = s_warp + 8;                      // [2][8]
    u64*   s_mbar = s_key + 16;                      // [2]

    // full coord table: every CTA holds the whole batch (192KB, one-time)
    for (int i = tid; i < N; i += FPS_THR) {
        s_fx[i] = pb[i * 3 + 0];
        s_fy[i] = pb[i * 3 + 1];
        s_fz[i] = pb[i * 3 + 2];
    }

    // this CTA's 2048 points, register-resident, packed in pairs
    u64 ppx[4], ppy[4], ppz[4];
    float d[8];
#pragma unroll
    for (int p = 0; p < 4; ++p) {
        int i0 = base + (2 * p) * FPS_THR + tid;
        int i1 = base + (2 * p + 1) * FPS_THR + tid;
        float x0 = pb[i0 * 3 + 0], y0 = pb[i0 * 3 + 1], z0 = pb[i0 * 3 + 2];
        float x1 = pb[i1 * 3 + 0], y1 = pb[i1 * 3 + 1], z1 = pb[i1 * 3 + 2];
        PACK2V(ppx[p], x0, x1);
        PACK2V(ppy[p], y0, y1);
        PACK2V(ppz[p], z0, z1);
        d[2 * p] = 1e10f; d[2 * p + 1] = 1e10f;
    }

    const uint32_t mb0 = (uint32_t)__cvta_generic_to_shared(&s_mbar[0]);
    const uint32_t mb1 = (uint32_t)__cvta_generic_to_shared(&s_mbar[1]);
    if (tid == 0) {
        asm volatile("mbarrier.init.shared.b64 [%0], %1;" :: "r"(mb0), "r"((unsigned)FPS_CTAS) : "memory");
        asm volatile("mbarrier.init.shared.b64 [%0], %1;" :: "r"(mb1), "r"((unsigned)FPS_CTAS) : "memory");
    }
    __syncthreads();
    asm volatile("barrier.cluster.arrive.aligned;" ::: "memory");
    asm volatile("barrier.cluster.wait.aligned;"   ::: "memory");

    // warp0 lanes 0..7 publish this CTA's key to CTA 'lane' (slot rank)
    uint32_t rk[2], rm[2];
    if (wid == 0 && lane < FPS_CTAS) {
#pragma unroll
        for (int par = 0; par < 2; ++par) {
            uint32_t a = (uint32_t)__cvta_generic_to_shared(&s_key[par * FPS_CTAS + rank]);
            asm("mapa.shared::cluster.u32 %0, %1, %2;" : "=r"(rk[par]) : "r"(a), "r"(lane));
            a = (par == 0) ? mb0 : mb1;
            asm("mapa.shared::cluster.u32 %0, %1, %2;" : "=r"(rm[par]) : "r"(a), "r"(lane));
        }
    }

    // prologue: centroid 0 = point 0
    if (rank == 0 && tid == 0) g_idxc[batch * S] = 0;
    {
        u64 key = update_argmax(ppx, ppy, ppz, d, pb[0], pb[1], pb[2], base, tid);
        key = warp_max_key(key);
        if (lane == 0) s_warp[wid] = key;
    }

    for (int s = 0; s < S - 1; ++s) {
        __syncthreads();   // (A) — s_warp complete (8 warps)

        const int par = s & 1;
        if (wid == 0) {
            // block winner: 8 warp keys -> redux pair (exact tie-break)
            u64 kl = warp_max_key(s_warp[lane & 7]);
            if (lane < FPS_CTAS) {
                asm volatile("st.shared::cluster.b64 [%0], %1;" :: "r"(rk[par]), "l"(kl) : "memory");
                asm volatile("mbarrier.arrive.release.cluster.shared::cluster.b64 _, [%0];"
                             :: "r"(rm[par]) : "memory");
            }
            // single-waiter cluster-scope acquire (warp0 only)
            {
                const uint32_t mb = par ? mb1 : mb0;
                const uint32_t ph = (unsigned)(s >> 1) & 1u;
                uint32_t done;
                asm volatile(
                    "{\n\t.reg .pred p;\n\t"
                    "mbarrier.try_wait.parity.acquire.cluster.shared::cta.b64 p, [%1], %2;\n\t"
                    "selp.b32 %0, 1, 0, p;\n\t}"
                    : "=r"(done) : "r"(mb), "r"(ph) : "memory");
                if (!done) {
                    asm volatile(
                        "{\n\t.reg .pred P1;\n\t"
                        "WL%=:\n\t"
                        "mbarrier.try_wait.parity.acquire.cluster.shared::cta.b64 P1, [%0], %1, 0x989680;\n\t"
                        "@P1 bra.uni WD%=;\n\t"
                        "bra.uni WL%=;\n\t"
                        "WD%=:\n\t}"
                        :: "r"(mb), "r"(ph) : "memory");
                }
            }
        }
        __syncthreads();   // (B) — CTA fence releases remote slots to all warps

        // winner among 8 CTA candidates; coords from the local full table
        u64 bk = s_key[par * FPS_CTAS];
#pragma unroll
        for (int r = 1; r < FPS_CTAS; ++r) {
            u64 kk = s_key[par * FPS_CTAS + r];
            if (kk > bk) bk = kk;
        }
        unsigned widx = 0xffffffffu - (unsigned)bk;
        if (rank == 0 && tid == 0)
            g_idxc[batch * S + s + 1] = (int)widx;
        float cx = s_fx[widx], cy = s_fy[widx], cz = s_fz[widx];

        u64 key = update_argmax(ppx, ppy, ppz, d, cx, cy, cz, base, tid);
        key = warp_max_key(key);
        if (lane == 0) s_warp[wid] = key;
    }
}

// =====================================================================
// 2) gather centroids: new_xyz + transposed block of the output
// =====================================================================
__global__ void __launch_bounds__(256)
gather_kernel(const float* __restrict__ pos, float* __restrict__ out)
{
    using namespace cfg;
    int t = blockIdx.x * 256 + threadIdx.x;       // b*S+s
    int b = t / S, s = t - b * S;
    int id = g_idxc[t];
    const float* p = pos + ((size_t)b * N + id) * 3;
    float x = p[0], y = p[1], z = p[2];
    g_newxyz[t * 3 + 0] = x;
    g_newxyz[t * 3 + 1] = y;
    g_newxyz[t * 3 + 2] = z;
    out[((size_t)b * 3 + 0) * S + s] = x;
    out[((size_t)b * 3 + 1) * S + s] = y;
    out[((size_t)b * 3 + 2) * S + s] = z;
}

// =====================================================================
// 3) ball query: warp per centroid; first K in-radius indices ascending
// =====================================================================
__global__ void __launch_bounds__(256)
ballq_kernel(const float* __restrict__ pos)
{
    using namespace cfg;
    int g = blockIdx.x * 8 + (threadIdx.x >> 5);  // b*S+s
    int lane = threadIdx.x & 31;
    int b = g / S;
    float cx = g_newxyz[g * 3 + 0];
    float cy = g_newxyz[g * 3 + 1];
    float cz = g_newxyz[g * 3 + 2];
    float cn = __fadd_rn(__fadd_rn(__fmul_rn(cx, cx), __fmul_rn(cy, cy)), __fmul_rn(cz, cz));
    const float* pb = pos + (size_t)b * N * 3;
    int* outp = g_ballidx + (size_t)g * K;

    int filled = 0;
    int first = -1;
    for (int p0 = 0; p0 < N && filled < K; p0 += 32) {
        int p = p0 + lane;
        float px = pb[p * 3 + 0], py = pb[p * 3 + 1], pz = pb[p * 3 + 2];
        float pn = __fadd_rn(__fadd_rn(__fmul_rn(px, px), __fmul_rn(py, py)), __fmul_rn(pz, pz));
        float dot = __fadd_rn(__fadd_rn(__fmul_rn(cx, px), __fmul_rn(cy, py)), __fmul_rn(cz, pz));
        float sq = __fadd_rn(__fadd_rn(cn, pn), -__fmul_rn(2.0f, dot));
        bool incl = !(sq > R2);
        unsigned mask = __ballot_sync(FULLMASK, incl);
        if (first < 0 && mask) first = p0 + (__ffs(mask) - 1);
        int rnk = filled + __popc(mask & ((1u << lane) - 1u));
        if (incl && rnk < K) outp[rnk] = p;
        filled += __popc(mask);
    }
    if (first < 0) first = 0;
    if (filled < K)
        for (int j = filled + lane; j < K; j += 32) outp[j] = first;
}

// =====================================================================
// 4) layer1: gather groups + conv 6->64 (raw conv output, bias included)
// =====================================================================
__global__ void __launch_bounds__(256)
layer1_kernel(const float* __restrict__ pos, const float* __restrict__ feats,
              const float* __restrict__ w1, const float* __restrict__ b1)
{
    using namespace cfg;
    __shared__ float ws[64 * 6];
    __shared__ float bs[64];
    for (int i = threadIdx.x; i < 64 * 6; i += 256) ws[i] = w1[i];
    if (threadIdx.x < 64) bs[threadIdx.x] = b1[threadIdx.x];
    __syncthreads();

    int g = blockIdx.x * 8 + (threadIdx.x >> 5);  // b*S+s
    int lane = threadIdx.x & 31;                  // k within group
    int b = g / S;
    int id = g_ballidx[(size_t)g * K + lane];
    const float* p = pos   + ((size_t)b * N + id) * 3;
    const float* f = feats + ((size_t)b * N + id) * 3;
    float c0 = p[0] - g_newxyz[g * 3 + 0];
    float c1 = p[1] - g_newxyz[g * 3 + 1];
    float c2 = p[2] - g_newxyz[g * 3 + 2];
    float c3 = f[0], c4 = f[1], c5 = f[2];
    size_t ncol = (size_t)g * K + lane;
#pragma unroll
    for (int o = 0; o < 64; ++o) {
        const float* w = ws + o * 6;
        float acc = bs[o];
        acc = fmaf(w[0], c0, acc);
        acc = fmaf(w[1], c1, acc);
        acc = fmaf(w[2], c2, acc);
        acc = fmaf(w[3], c3, acc);
        acc = fmaf(w[4], c4, acc);
        acc = fmaf(w[5], c5, acc);
        g_x1[(size_t)o * NN + ncol] = acc;
    }
}

// =====================================================================
// 5) layer1 per-channel partial sums (64 chunks of 4096), chunk-major out
// =====================================================================
__global__ void __launch_bounds__(256)
stats_part1_kernel()
{
    using namespace cfg;
    int c = blockIdx.y, chunk = blockIdx.x;
    const float* p = g_x1 + (size_t)c * NN + (size_t)chunk * 4096;
    int t = threadIdx.x;
    float s = 0.f, q = 0.f;
#pragma unroll
    for (int i = 0; i < 4; ++i) {
        float4 v = *(const float4*)&p[i * 1024 + t * 4];
        s += v.x; s += v.y; s += v.z; s += v.w;
        q += v.x * v.x; q += v.y * v.y; q += v.z * v.z; q += v.w * v.w;
    }
#pragma unroll
    for (int off = 16; off; off >>= 1) {
        s += __shfl_down_sync(FULLMASK, s, off);
        q += __shfl_down_sync(FULLMASK, q, off);
    }
    __shared__ float ss[8], qq[8];
    if ((t & 31) == 0) { ss[t >> 5] = s; qq[t >> 5] = q; }
    __syncthreads();
    if (t == 0) {
        float S2 = 0.f, Q2 = 0.f;
#pragma unroll
        for (int i = 0; i < 8; ++i) { S2 += ss[i]; Q2 += qq[i]; }
        g_psum[chunk * 256 + c] = S2;   // chunk-major: coalesced finalize
        g_psq [chunk * 256 + c] = Q2;
    }
}

// finalize: mu, var -> folded scale/shift  y = relu(A*x + Bc)
template<int NPART>
__global__ void __launch_bounds__(256)
stats_fin_kernel(const float* __restrict__ gamma, const float* __restrict__ beta, int C)
{
    using namespace cfg;
    int c = blockIdx.x * 256 + threadIdx.x;
    if (c >= C) return;
    float s = 0.f, q = 0.f;
#pragma unroll 8
    for (int i = 0; i < NPART; ++i) { s += g_psum[i * 256 + c]; q += g_psq[i * 256 + c]; }
    const float inv = 1.0f / (float)NN;   // 2^-18, exact
    float mu  = s * inv;
    float var = q * inv - mu * mu;
    float rs  = rsqrtf(var + EPS);
    float A   = gamma[c] * rs;
    g_A[c]  = A;
    g_Bc[c] = beta[c] - mu * A;
}

// =====================================================================
// 6) GEMM (R13-proven single-buffer): 128x128 tile, FFMA2 inner loop.
// =====================================================================
template<int LAYER>
__global__ void __launch_bounds__(256)
gemm_kernel(const float* __restrict__ W, const float* __restrict__ bias)
{
    using namespace cfg;
    constexpr int Cin = (LAYER == 2) ? 64 : 128;
    const float* __restrict__ X = (LAYER == 2) ? g_x1 : g_x2;
    float* __restrict__ Y       = g_x2;   // only used for LAYER==2

    __shared__ float sA[8][128];
    __shared__ float sB[8][132];
    const int tid = threadIdx.x;
    const int n0 = blockIdx.x * 128;
    const int m0 = blockIdx.y * 128;
    const int tm = (tid >> 4) << 3;
    const int tn = (tid & 15) << 3;

    u64 acc2[8][4];
#pragma unroll
    for (int i = 0; i < 8; ++i) {
        float bv = bias[m0 + tm + i];
        u64 p; PACK2(p, bv);
#pragma unroll
        for (int j = 0; j < 4; ++j) acc2[i][j] = p;
    }

    const int kload_m = tid >> 1;            // 0..127
    const int kload_k = (tid & 1) << 2;      // 0 or 4
    const int bload_k = tid >> 5;            // 0..7
    const int bload_n = (tid & 31) << 2;     // 0..124

    for (int kt = 0; kt < Cin; kt += 8) {
        float4 wv = *(const float4*)&W[(size_t)(m0 + kload_m) * Cin + kt + kload_k];
        float a_s = g_A [kt + bload_k];
        float b_s = g_Bc[kt + bload_k];
        float4 xv = *(const float4*)&X[(size_t)(kt + bload_k) * NN + n0 + bload_n];
        sA[kload_k + 0][kload_m] = wv.x;
        sA[kload_k + 1][kload_m] = wv.y;
        sA[kload_k + 2][kload_m] = wv.z;
        sA[kload_k + 3][kload_m] = wv.w;
        float4 yv;
        yv.x = fmaxf(fmaf(a_s, xv.x, b_s), 0.f);
        yv.y = fmaxf(fmaf(a_s, xv.y, b_s), 0.f);
        yv.z = fmaxf(fmaf(a_s, xv.z, b_s), 0.f);
        yv.w = fmaxf(fmaf(a_s, xv.w, b_s), 0.f);
        *(float4*)&sB[bload_k][bload_n] = yv;
        __syncthreads();
#pragma unroll
        for (int kk = 0; kk < 8; ++kk) {
            float av[8];
            *(float4*)(av)     = *(const float4*)&sA[kk][tm];
            *(float4*)(av + 4) = *(const float4*)&sA[kk][tm + 4];
            const u64* bp = (const u64*)&sB[kk][tn];   // 32B-aligned
            u64 b2[4] = { bp[0], bp[1], bp[2], bp[3] };
#pragma unroll
            for (int i = 0; i < 8; ++i) {
                u64 a2; PACK2(a2, av[i]);
#pragma unroll
                for (int j = 0; j < 4; ++j)
                    FFMA2(acc2[i][j], a2, b2[j], acc2[i][j]);
            }
        }
        __syncthreads();
    }

    // ----- epilogue: store (L2), stats partials (all), group max (L3) -----
    const int bx = blockIdx.x;
#pragma unroll
    for (int i = 0; i < 8; ++i) {
        float v[8];
        v[0] = lo32(acc2[i][0]); v[1] = hi32(acc2[i][0]);
        v[2] = lo32(acc2[i][1]); v[3] = hi32(acc2[i][1]);
        v[4] = lo32(acc2[i][2]); v[5] = hi32(acc2[i][2]);
        v[6] = lo32(acc2[i][3]); v[7] = hi32(acc2[i][3]);
        if constexpr (LAYER == 2) {
            size_t row = (size_t)(m0 + tm + i) * NN + n0 + tn;
            *(float4*)&Y[row]     = make_float4(v[0], v[1], v[2], v[3]);
            *(float4*)&Y[row + 4] = make_float4(v[4], v[5], v[6], v[7]);
        }
        float s = 0.f, q = 0.f;
#pragma unroll
        for (int j = 0; j < 8; ++j) { s += v[j]; q += v[j] * v[j]; }
#pragma unroll
        for (int off = 1; off < 16; off <<= 1) {
            s += __shfl_xor_sync(FULLMASK, s, off);
            q += __shfl_xor_sync(FULLMASK, q, off);
        }
        if ((tid & 15) == 0) {
            g_psum[bx * 256 + (m0 + tm + i)] = s;   // chunk-major
            g_psq [bx * 256 + (m0 + tm + i)] = q;
        }
        if constexpr (LAYER == 3) {
            float mx = v[0];
#pragma unroll
            for (int j = 1; j < 8; ++j) mx = fmaxf(mx, v[j]);
            mx = fmaxf(mx, __shfl_xor_sync(FULLMASK, mx, 1));
            mx = fmaxf(mx, __shfl_xor_sync(FULLMASK, mx, 2));
            if ((tid & 3) == 0)
                g_max[(size_t)(m0 + tm + i) * BS + (n0 >> 5) + ((tid & 15) >> 2)] = mx;
        }
    }
}

// =====================================================================
// 7) final: y = relu(A3*mx + B3) over the 8MB group-max buffer
// =====================================================================
__global__ void __launch_bounds__(256)
finalmax_kernel(float* __restrict__ out)
{
    using namespace cfg;
    int idx = blockIdx.x * 256 + threadIdx.x;   // c*8192 + bs
    int c  = idx >> 13;
    int bs = idx & 8191;
    float mx = g_max[(size_t)c * BS + bs];
    float y = fmaxf(fmaf(g_A[c], mx, g_Bc[c]), 0.f);
    int b = bs >> 11, s = bs & 2047;
    out[(size_t)B * 3 * S + ((size_t)b * 256 + c) * S + s] = y;
}

// =====================================================================
// launcher
// =====================================================================
extern "C" void kernel_launch(void* const* d_in, const int* in_sizes, int n_in,
                              void* d_out, int out_size)
{
    using namespace cfg;
    const float* pos   = (const float*)d_in[0];
    const float* feats = (const float*)d_in[1];
    const float* w1 = (const float*)d_in[2];
    const float* b1 = (const float*)d_in[3];
    const float* g1 = (const float*)d_in[4];
    const float* be1 = (const float*)d_in[5];
    const float* w2 = (const float*)d_in[6];
    const float* b2 = (const float*)d_in[7];
    const float* g2 = (const float*)d_in[8];
    const float* be2 = (const float*)d_in[9];
    const float* w3 = (const float*)d_in[10];
    const float* b3 = (const float*)d_in[11];
    const float* g3 = (const float*)d_in[12];
    const float* be3 = (const float*)d_in[13];
    float* out = (float*)d_out;

    // full coord table (192KB) + warp keys + exchange slots + mbarriers
    const int fps_smem = 3 * N * 4 + 512;
    cudaFuncSetAttribute(fps_kernel, cudaFuncAttributeMaxDynamicSharedMemorySize, fps_smem);

    // shims: keep fps_kernel in the fixed ncu capture slot
    noop_kernel<<<1, 32>>>(0);
    noop_kernel<<<1, 32>>>(0);
    noop_kernel<<<1, 32>>>(0);

    fps_kernel<<<B * FPS_CTAS, FPS_THR, fps_smem>>>(pos);
    gather_kernel<<<BS / 256, 256>>>(pos, out);
    ballq_kernel<<<BS / 8, 256>>>(pos);
    layer1_kernel<<<BS / 8, 256>>>(pos, feats, w1, b1);

    stats_part1_kernel<<<dim3(64, 64), 256>>>();
    stats_fin_kernel<64><<<1, 256>>>(g1, be1, 64);

    gemm_kernel<2><<<dim3(NN / 128, 1), 256>>>(w2, b2);
    stats_fin_kernel<2048><<<1, 256>>>(g2, be2, 128);

    gemm_kernel<3><<<dim3(NN / 128, 2), 256>>>(w3, b3);
    stats_fin_kernel<2048><<<1, 256>>>(g3, be3, 256);

    finalmax_kernel<<<(256 * BS) / 256, 256>>>(out);
}